// round 14
// baseline (speedup 1.0000x reference)
#include <cuda_runtime.h>

// CalibrationLayer R14: cp.async-staged streamer (per-thread FIFO, depth 5)
// + shared-search build.
//
//  k1 build_pack: ri staged in shared; thread-per-bucket binary search;
//     packs rec(b)=(qy<<16)|(qy(b+1)-qy(b)) -> g_tab. (unchanged, ~1.9us)
//  k2 calib_main: table in shared (57KB) + 6 x 8KB x-stages. Each thread owns
//     one 16B slot per stage and runs a PRIVATE cp.async pipeline:
//       issue cp.async.cg(tile k+5) ; commit ; wait_group 4 ; LDS own slot of
//       tile k ; eval x4 ; __stcs out.
//     No __syncthreads / mbarriers in the hot loop. In-flight per SM =
//     1024 thr x 5 x 16B = 80KB (~640 lines) -> DRAM latency fully hidden
//     (R13 register-prefetch managed only ~100 lines and stayed exposed).
// Accuracy: chord dev ~5e-6 + quant 8e-6 abs << 1e-3; fb-clamp gives exact
// end-clamps.

#define KBUCK   14336
#define QS      65535.0f
#define QINV    (1.0f / 65535.0f)
#define RMAX    4096

#define BUILD_THREADS 512

#define MAIN_THREADS 512
#define MAIN_CTAS    2
#define MAIN_GRID    (148 * MAIN_CTAS)
#define NSTAGE  6
#define ADEPTH  5                         // groups in flight (<= NSTAGE-1)
#define SMEM_BYTES (KBUCK * 4 + NSTAGE * MAIN_THREADS * 16)

__device__ unsigned int g_tab[KBUCK];

// ---- kernel 1: build + pack, binary search in shared ----
__global__ __launch_bounds__(BUILD_THREADS)
void build_pack(const float* __restrict__ ri,
                const float* __restrict__ ro, int R) {
    __shared__ float sri[RMAX];
    const int rcap = (R < RMAX) ? R : RMAX;
    for (int i = threadIdx.x; i < rcap; i += BUILD_THREADS)
        sri[i] = ri[i];
    __syncthreads();

    const float lo = sri[0];
    const float hi = sri[R - 1];
    const float w  = (hi - lo) / (float)KBUCK;

    auto edge_val = [&](int e) -> float {
        float ex = fmaf((float)e, w, lo);
        int a = 0, b = R - 1;
        while (b - a > 1) {
            int m = (a + b) >> 1;
            if (sri[m] <= ex) a = m; else b = m;
        }
        float xt = sri[a], xp = sri[a + 1];
        float yt = __ldg(ro + a), yp = __ldg(ro + a + 1);
        return yt + (yp - yt) * __fdividef(ex - xt, xp - xt);
    };

    int bk = blockIdx.x * BUILD_THREADS + threadIdx.x;
    if (bk < KBUCK) {
        float yl = edge_val(bk);
        float yh = edge_val(bk + 1);
        int ql = min(max(__float2int_rn(yl * QS), 0), 65535);
        int qh = min(max(__float2int_rn(yh * QS), 0), 65535);
        g_tab[bk] = ((unsigned int)ql << 16) | (unsigned int)(qh - ql);
    }
}

// ---- cp.async helpers ----
__device__ __forceinline__ void cp_async16(unsigned int saddr, const void* gptr) {
    asm volatile("cp.async.cg.shared.global [%0], [%1], 16;"
                 :: "r"(saddr), "l"(gptr));
}
__device__ __forceinline__ void cp_commit() {
    asm volatile("cp.async.commit_group;");
}
__device__ __forceinline__ void cp_wait_all_but(int) {}  // (unused)
#define CP_WAIT_4() asm volatile("cp.async.wait_group 4;")

// ---- kernel 2: streamer ----
extern __shared__ unsigned char smem_raw[];

__global__ __launch_bounds__(MAIN_THREADS, MAIN_CTAS)
void calib_main(const float* __restrict__ x,
                const float* __restrict__ ri,
                float* __restrict__ out,
                int n, int R) {
    unsigned int* tb = (unsigned int*)smem_raw;
    float4* stage = (float4*)(smem_raw + KBUCK * 4);

    // cooperative table load (coalesced, L2-hot)
    {
        const uint4* __restrict__ src = (const uint4*)g_tab;
        uint4* __restrict__ dst = (uint4*)tb;
        #pragma unroll
        for (int k = 0; k < KBUCK / 4 / MAIN_THREADS; ++k)
            dst[k * MAIN_THREADS + threadIdx.x] = src[k * MAIN_THREADS + threadIdx.x];
    }
    __syncthreads();

    const float lo   = __ldg(&ri[0]);
    const float hi   = __ldg(&ri[R - 1]);
    const float invw = (float)KBUCK / (hi - lo);
    const float nglo = -lo * invw;
    const float fK   = (float)KBUCK;

    auto eval = [&](float xv) -> float {
        float fb = fmaf(xv, invw, nglo);
        fb = fminf(fmaxf(fb, 0.0f), fK);          // exact end-clamps
        int b = (int)fb;
        b = min(b, KBUCK - 1);
        unsigned int rec = tb[b];                 // LDS.32
        float frac = fb - (float)b;
        float qy = (float)(rec >> 16);
        float qd = (float)(rec & 0xFFFFu);
        return fmaf(qd, frac, qy) * QINV;
    };

    const int tid    = (int)threadIdx.x;
    const int n4     = n >> 2;
    const int ntiles = n4 / MAIN_THREADS;         // full tiles of 512 float4
    const float4* __restrict__ x4 = (const float4*)x;
    float4* __restrict__ o4 = (float4*)out;

    // per-thread slot addresses (shared state space)
    unsigned int slot0 = (unsigned int)__cvta_generic_to_shared(stage + tid);
    const unsigned int slot_stride = MAIN_THREADS * 16;   // bytes per stage

    // ---- prologue: issue ADEPTH tiles (empty commits keep counts aligned) ----
    #pragma unroll
    for (int j = 0; j < ADEPTH; ++j) {
        int T = blockIdx.x + j * MAIN_GRID;
        if (T < ntiles)
            cp_async16(slot0 + (unsigned)j * slot_stride,
                       x4 + (size_t)T * MAIN_THREADS + tid);
        cp_commit();
    }

    // ---- steady state: private FIFO, no block syncs ----
    int slot = 0;                                  // k % NSTAGE
    int slot_issue = ADEPTH;                       // (k+ADEPTH) % NSTAGE
    for (int k = 0; ; ++k) {
        int T = blockIdx.x + k * MAIN_GRID;
        if (T >= ntiles) break;
        CP_WAIT_4();                               // oldest group (tile k) done
        float4 v = stage[slot * MAIN_THREADS + tid];
        float4 o;
        o.x = eval(v.x); o.y = eval(v.y); o.z = eval(v.z); o.w = eval(v.w);
        __stcs(&o4[(size_t)T * MAIN_THREADS + tid], o);
        int Tn = blockIdx.x + (k + ADEPTH) * MAIN_GRID;
        if (Tn < ntiles)
            cp_async16(slot0 + (unsigned)slot_issue * slot_stride,
                       x4 + (size_t)Tn * MAIN_THREADS + tid);
        cp_commit();
        slot = (slot + 1 == NSTAGE) ? 0 : slot + 1;
        slot_issue = (slot_issue + 1 == NSTAGE) ? 0 : slot_issue + 1;
    }

    // ---- remainder float4s + scalar tail: block 0, direct ----
    if (blockIdx.x == 0) {
        for (int i = ntiles * MAIN_THREADS + tid; i < n4; i += MAIN_THREADS) {
            float4 v = __ldg(&x4[i]);
            float4 o;
            o.x = eval(v.x); o.y = eval(v.y); o.z = eval(v.z); o.w = eval(v.w);
            o4[i] = o;
        }
        for (int j = (n4 << 2) + tid; j < n; j += MAIN_THREADS)
            out[j] = eval(__ldg(&x[j]));
    }
}

extern "C" void kernel_launch(void* const* d_in, const int* in_sizes, int n_in,
                              void* d_out, int out_size) {
    const float* x  = (const float*)d_in[0];
    const float* ri = (const float*)d_in[1];
    const float* ro = (const float*)d_in[2];
    float* out      = (float*)d_out;
    const int n = in_sizes[0];
    const int R = in_sizes[1];

    build_pack<<<KBUCK / BUILD_THREADS, BUILD_THREADS>>>(ri, ro, R);
    cudaFuncSetAttribute(calib_main, cudaFuncAttributeMaxDynamicSharedMemorySize,
                         SMEM_BYTES);
    calib_main<<<MAIN_GRID, MAIN_THREADS, SMEM_BYTES>>>(x, ri, out, n, R);
}

// round 15
// speedup vs baseline: 1.0019x; 1.0019x over previous
#include <cuda_runtime.h>

// CalibrationLayer R15: K=8192 table (32KB) -> 3 CTAs/SM cp.async streamer.
//
//  k1 build_pack: one thread per bucket (8192 thr = 64x128), two interleaved
//     binary searches over L2-hot ri; packs rec(b)=(qy<<16)|qd -> g_tab.
//  k2 calib_main: 32KB table in shared + 4 x 8KB x-stages; per-thread private
//     cp.async FIFO depth 3 (no block syncs in hot loop). 512 thr x 3 CTAs/SM
//     = 1536 thr/SM (24 warps/SMSP vs R14's 16) while keeping 72KB/SM of
//     x-bytes in flight.
// Accuracy: chord dev ~1.6e-5 + quant 8e-6 abs << 1e-3; fb-clamp gives exact
// end-clamps (edge values = ro endpoints).

#define KBUCK   8192
#define QS      65535.0f
#define QINV    (1.0f / 65535.0f)

#define MAIN_THREADS 512
#define MAIN_CTAS    3
#define MAIN_GRID    (148 * MAIN_CTAS)
#define NSTAGE  4
#define ADEPTH  3                         // groups in flight
#define SMEM_BYTES (KBUCK * 4 + NSTAGE * MAIN_THREADS * 16)

__device__ unsigned int g_tab[KBUCK];

// ---- kernel 1: build + pack, one thread per bucket, ILP-2 searches ----
__global__ __launch_bounds__(128)
void build_pack(const float* __restrict__ ri,
                const float* __restrict__ ro, int R) {
    int bk = blockIdx.x * 128 + threadIdx.x;
    if (bk >= KBUCK) return;

    const float lo = __ldg(&ri[0]);
    const float hi = __ldg(&ri[R - 1]);
    const float w  = (hi - lo) / (float)KBUCK;

    float ex0 = fmaf((float)bk,       w, lo);
    float ex1 = fmaf((float)(bk + 1), w, lo);

    // two independent binary searches, interleaved for ILP
    int a0 = 0, b0 = R - 1, a1 = 0, b1 = R - 1;
    while ((b0 - a0 > 1) | (b1 - a1 > 1)) {
        if (b0 - a0 > 1) {
            int m = (a0 + b0) >> 1;
            if (__ldg(ri + m) <= ex0) a0 = m; else b0 = m;
        }
        if (b1 - a1 > 1) {
            int m = (a1 + b1) >> 1;
            if (__ldg(ri + m) <= ex1) a1 = m; else b1 = m;
        }
    }
    float xt0 = __ldg(ri + a0), xp0 = __ldg(ri + a0 + 1);
    float yt0 = __ldg(ro + a0), yp0 = __ldg(ro + a0 + 1);
    float yl = yt0 + (yp0 - yt0) * __fdividef(ex0 - xt0, xp0 - xt0);

    float xt1 = __ldg(ri + a1), xp1 = __ldg(ri + a1 + 1);
    float yt1 = __ldg(ro + a1), yp1 = __ldg(ro + a1 + 1);
    float yh = yt1 + (yp1 - yt1) * __fdividef(ex1 - xt1, xp1 - xt1);

    int ql = min(max(__float2int_rn(yl * QS), 0), 65535);
    int qh = min(max(__float2int_rn(yh * QS), 0), 65535);
    g_tab[bk] = ((unsigned int)ql << 16) | (unsigned int)(qh - ql);
}

// ---- cp.async helpers ----
__device__ __forceinline__ void cp_async16(unsigned int saddr, const void* gptr) {
    asm volatile("cp.async.cg.shared.global [%0], [%1], 16;"
                 :: "r"(saddr), "l"(gptr));
}
__device__ __forceinline__ void cp_commit() {
    asm volatile("cp.async.commit_group;");
}
#define CP_WAIT_OLDEST() asm volatile("cp.async.wait_group 2;")

// ---- kernel 2: streamer ----
extern __shared__ unsigned char smem_raw[];

__global__ __launch_bounds__(MAIN_THREADS, MAIN_CTAS)
void calib_main(const float* __restrict__ x,
                const float* __restrict__ ri,
                float* __restrict__ out,
                int n, int R) {
    unsigned int* tb = (unsigned int*)smem_raw;
    float4* stage = (float4*)(smem_raw + KBUCK * 4);

    // cooperative table load (coalesced, L2-hot)
    {
        const uint4* __restrict__ src = (const uint4*)g_tab;
        uint4* __restrict__ dst = (uint4*)tb;
        #pragma unroll
        for (int k = 0; k < KBUCK / 4 / MAIN_THREADS; ++k)
            dst[k * MAIN_THREADS + threadIdx.x] = src[k * MAIN_THREADS + threadIdx.x];
    }
    __syncthreads();

    const float lo   = __ldg(&ri[0]);
    const float hi   = __ldg(&ri[R - 1]);
    const float invw = (float)KBUCK / (hi - lo);
    const float nglo = -lo * invw;
    const float fK   = (float)KBUCK;

    auto eval = [&](float xv) -> float {
        float fb = fmaf(xv, invw, nglo);
        fb = fminf(fmaxf(fb, 0.0f), fK);          // exact end-clamps
        int b = (int)fb;
        b = min(b, KBUCK - 1);
        unsigned int rec = tb[b];                 // LDS.32
        float frac = fb - (float)b;
        float qy = (float)(rec >> 16);
        float qd = (float)(rec & 0xFFFFu);
        return fmaf(qd, frac, qy) * QINV;
    };

    const int tid    = (int)threadIdx.x;
    const int n4     = n >> 2;
    const int ntiles = n4 / MAIN_THREADS;         // full tiles of 512 float4
    const float4* __restrict__ x4 = (const float4*)x;
    float4* __restrict__ o4 = (float4*)out;

    unsigned int slot0 = (unsigned int)__cvta_generic_to_shared(stage + tid);
    const unsigned int slot_stride = MAIN_THREADS * 16;

    // prologue: issue ADEPTH tiles (empty commits keep group counts aligned)
    #pragma unroll
    for (int j = 0; j < ADEPTH; ++j) {
        int T = blockIdx.x + j * MAIN_GRID;
        if (T < ntiles)
            cp_async16(slot0 + (unsigned)j * slot_stride,
                       x4 + (size_t)T * MAIN_THREADS + tid);
        cp_commit();
    }

    // steady state: private FIFO, no block syncs
    int slot = 0, slot_issue = ADEPTH;
    for (int k = 0; ; ++k) {
        int T = blockIdx.x + k * MAIN_GRID;
        if (T >= ntiles) break;
        CP_WAIT_OLDEST();                          // tile k landed
        float4 v = stage[slot * MAIN_THREADS + tid];
        float4 o;
        o.x = eval(v.x); o.y = eval(v.y); o.z = eval(v.z); o.w = eval(v.w);
        __stcs(&o4[(size_t)T * MAIN_THREADS + tid], o);
        int Tn = blockIdx.x + (k + ADEPTH) * MAIN_GRID;
        if (Tn < ntiles)
            cp_async16(slot0 + (unsigned)slot_issue * slot_stride,
                       x4 + (size_t)Tn * MAIN_THREADS + tid);
        cp_commit();
        slot = (slot + 1 == NSTAGE) ? 0 : slot + 1;
        slot_issue = (slot_issue + 1 == NSTAGE) ? 0 : slot_issue + 1;
    }

    // remainder float4s + scalar tail: block 0, direct
    if (blockIdx.x == 0) {
        for (int i = ntiles * MAIN_THREADS + tid; i < n4; i += MAIN_THREADS) {
            float4 v = __ldg(&x4[i]);
            float4 o;
            o.x = eval(v.x); o.y = eval(v.y); o.z = eval(v.z); o.w = eval(v.w);
            o4[i] = o;
        }
        for (int j = (n4 << 2) + tid; j < n; j += MAIN_THREADS)
            out[j] = eval(__ldg(&x[j]));
    }
}

extern "C" void kernel_launch(void* const* d_in, const int* in_sizes, int n_in,
                              void* d_out, int out_size) {
    const float* x  = (const float*)d_in[0];
    const float* ri = (const float*)d_in[1];
    const float* ro = (const float*)d_in[2];
    float* out      = (float*)d_out;
    const int n = in_sizes[0];
    const int R = in_sizes[1];

    build_pack<<<KBUCK / 128, 128>>>(ri, ro, R);
    cudaFuncSetAttribute(calib_main, cudaFuncAttributeMaxDynamicSharedMemorySize,
                         SMEM_BYTES);
    calib_main<<<MAIN_GRID, MAIN_THREADS, SMEM_BYTES>>>(x, ri, out, n, R);
}

// round 16
// speedup vs baseline: 1.0190x; 1.0171x over previous
#include <cuda_runtime.h>

// CalibrationLayer R16: R12's shared-staged build + R15's 3-CTA cp.async
// streamer with a deeper (5-stage / depth-4) private FIFO.
//
//  k1 build_pack: 16 blocks x 512 thr; each block stages ri (16KB) in shared;
//     one thread per bucket runs two binary searches IN SHARED (29-cyc hops,
//     not 250-600-cyc L2/DRAM hops — R15's build regression);
//     packs rec(b) = (round(ylo*65535)<<16) | (qy(b+1)-qy(b)) -> g_tab.
//  k2 calib_main: 32KB table in shared + 5 x 8KB x-stages; per-thread private
//     cp.async FIFO depth 4 (wait_group 3), no block syncs in the hot loop.
//     512 thr x 3 CTAs/SM (24 warps/SMSP), 96KB/SM x-bytes in flight.
// Accuracy: chord dev ~1.6e-5 + quant 8e-6 abs << 1e-3; fb-clamp gives exact
// end-clamps (edge values = ro endpoints).

#define KBUCK   8192
#define QS      65535.0f
#define QINV    (1.0f / 65535.0f)
#define RMAX    4096

#define BUILD_THREADS 512

#define MAIN_THREADS 512
#define MAIN_CTAS    3
#define MAIN_GRID    (148 * MAIN_CTAS)
#define NSTAGE  5
#define ADEPTH  4                         // groups in flight
#define SMEM_BYTES (KBUCK * 4 + NSTAGE * MAIN_THREADS * 16)   // 72KB

__device__ unsigned int g_tab[KBUCK];

// ---- kernel 1: build + pack, binary search in shared ----
__global__ __launch_bounds__(BUILD_THREADS)
void build_pack(const float* __restrict__ ri,
                const float* __restrict__ ro, int R) {
    __shared__ float sri[RMAX];
    const int rcap = (R < RMAX) ? R : RMAX;
    for (int i = threadIdx.x; i < rcap; i += BUILD_THREADS)
        sri[i] = ri[i];
    __syncthreads();

    const float lo = sri[0];
    const float hi = sri[R - 1];
    const float w  = (hi - lo) / (float)KBUCK;

    auto edge_val = [&](int e) -> float {
        float ex = fmaf((float)e, w, lo);
        int a = 0, b = R - 1;
        while (b - a > 1) {
            int m = (a + b) >> 1;
            if (sri[m] <= ex) a = m; else b = m;
        }
        float xt = sri[a], xp = sri[a + 1];
        float yt = __ldg(ro + a), yp = __ldg(ro + a + 1);
        return yt + (yp - yt) * __fdividef(ex - xt, xp - xt);
    };

    int bk = blockIdx.x * BUILD_THREADS + threadIdx.x;
    if (bk < KBUCK) {
        float yl = edge_val(bk);
        float yh = edge_val(bk + 1);
        int ql = min(max(__float2int_rn(yl * QS), 0), 65535);
        int qh = min(max(__float2int_rn(yh * QS), 0), 65535);
        g_tab[bk] = ((unsigned int)ql << 16) | (unsigned int)(qh - ql);
    }
}

// ---- cp.async helpers ----
__device__ __forceinline__ void cp_async16(unsigned int saddr, const void* gptr) {
    asm volatile("cp.async.cg.shared.global [%0], [%1], 16;"
                 :: "r"(saddr), "l"(gptr));
}
__device__ __forceinline__ void cp_commit() {
    asm volatile("cp.async.commit_group;");
}
#define CP_WAIT_OLDEST() asm volatile("cp.async.wait_group 3;")

// ---- kernel 2: streamer ----
extern __shared__ unsigned char smem_raw[];

__global__ __launch_bounds__(MAIN_THREADS, MAIN_CTAS)
void calib_main(const float* __restrict__ x,
                const float* __restrict__ ri,
                float* __restrict__ out,
                int n, int R) {
    unsigned int* tb = (unsigned int*)smem_raw;
    float4* stage = (float4*)(smem_raw + KBUCK * 4);

    // cooperative table load (coalesced, L2-hot)
    {
        const uint4* __restrict__ src = (const uint4*)g_tab;
        uint4* __restrict__ dst = (uint4*)tb;
        #pragma unroll
        for (int k = 0; k < KBUCK / 4 / MAIN_THREADS; ++k)
            dst[k * MAIN_THREADS + threadIdx.x] = src[k * MAIN_THREADS + threadIdx.x];
    }
    __syncthreads();

    const float lo   = __ldg(&ri[0]);
    const float hi   = __ldg(&ri[R - 1]);
    const float invw = (float)KBUCK / (hi - lo);
    const float nglo = -lo * invw;
    const float fK   = (float)KBUCK;

    auto eval = [&](float xv) -> float {
        float fb = fmaf(xv, invw, nglo);
        fb = fminf(fmaxf(fb, 0.0f), fK);          // exact end-clamps
        int b = (int)fb;
        b = min(b, KBUCK - 1);
        unsigned int rec = tb[b];                 // LDS.32
        float frac = fb - (float)b;
        float qy = (float)(rec >> 16);
        float qd = (float)(rec & 0xFFFFu);
        return fmaf(qd, frac, qy) * QINV;
    };

    const int tid    = (int)threadIdx.x;
    const int n4     = n >> 2;
    const int ntiles = n4 / MAIN_THREADS;         // full tiles of 512 float4
    const float4* __restrict__ x4 = (const float4*)x;
    float4* __restrict__ o4 = (float4*)out;

    unsigned int slot0 = (unsigned int)__cvta_generic_to_shared(stage + tid);
    const unsigned int slot_stride = MAIN_THREADS * 16;

    // prologue: issue ADEPTH tiles (empty commits keep group counts aligned)
    #pragma unroll
    for (int j = 0; j < ADEPTH; ++j) {
        int T = blockIdx.x + j * MAIN_GRID;
        if (T < ntiles)
            cp_async16(slot0 + (unsigned)j * slot_stride,
                       x4 + (size_t)T * MAIN_THREADS + tid);
        cp_commit();
    }

    // steady state: private FIFO, no block syncs
    int slot = 0, slot_issue = ADEPTH;
    for (int k = 0; ; ++k) {
        int T = blockIdx.x + k * MAIN_GRID;
        if (T >= ntiles) break;
        CP_WAIT_OLDEST();                          // tile k landed
        float4 v = stage[slot * MAIN_THREADS + tid];
        float4 o;
        o.x = eval(v.x); o.y = eval(v.y); o.z = eval(v.z); o.w = eval(v.w);
        __stcs(&o4[(size_t)T * MAIN_THREADS + tid], o);
        int Tn = blockIdx.x + (k + ADEPTH) * MAIN_GRID;
        if (Tn < ntiles)
            cp_async16(slot0 + (unsigned)slot_issue * slot_stride,
                       x4 + (size_t)Tn * MAIN_THREADS + tid);
        cp_commit();
        slot = (slot + 1 == NSTAGE) ? 0 : slot + 1;
        slot_issue = (slot_issue + 1 == NSTAGE) ? 0 : slot_issue + 1;
    }

    // remainder float4s + scalar tail: block 0, direct
    if (blockIdx.x == 0) {
        for (int i = ntiles * MAIN_THREADS + tid; i < n4; i += MAIN_THREADS) {
            float4 v = __ldg(&x4[i]);
            float4 o;
            o.x = eval(v.x); o.y = eval(v.y); o.z = eval(v.z); o.w = eval(v.w);
            o4[i] = o;
        }
        for (int j = (n4 << 2) + tid; j < n; j += MAIN_THREADS)
            out[j] = eval(__ldg(&x[j]));
    }
}

extern "C" void kernel_launch(void* const* d_in, const int* in_sizes, int n_in,
                              void* d_out, int out_size) {
    const float* x  = (const float*)d_in[0];
    const float* ri = (const float*)d_in[1];
    const float* ro = (const float*)d_in[2];
    float* out      = (float*)d_out;
    const int n = in_sizes[0];
    const int R = in_sizes[1];

    build_pack<<<KBUCK / BUILD_THREADS, BUILD_THREADS>>>(ri, ro, R);
    cudaFuncSetAttribute(calib_main, cudaFuncAttributeMaxDynamicSharedMemorySize,
                         SMEM_BYTES);
    calib_main<<<MAIN_GRID, MAIN_THREADS, SMEM_BYTES>>>(x, ri, out, n, R);
}